// round 1
// baseline (speedup 1.0000x reference)
#include <cuda_runtime.h>
#include <cuda_bf16.h>

#define NSEG 2048
#define EPS 1e-6f

// ---- scratch (device globals: no allocation allowed in kernel_launch) ----
__device__ float g_sumA[NSEG];   // sum over nodes of mean_c(s)
__device__ float g_sumB[NSEG];   // sum over nodes of mean_c(s^2)
__device__ float g_sumW[NSEG];   // sum over nodes of mean_c(sum_d v^2)
__device__ float g_cnt [NSEG];
__device__ float g_smean[NSEG];
__device__ float g_invvar[NSEG];
__device__ float g_invvm [NSEG];

__global__ void zero_kernel() {
    int i = blockIdx.x * blockDim.x + threadIdx.x;
    if (i < NSEG) {
        g_sumA[i] = 0.f; g_sumB[i] = 0.f; g_sumW[i] = 0.f; g_cnt[i] = 0.f;
    }
}

__device__ __forceinline__ float dot4(float4 a, float4 b) {
    return a.x * b.x + a.y * b.y + a.z * b.z + a.w * b.w;
}
__device__ __forceinline__ float sum4(float4 a) {
    return a.x + a.y + a.z + a.w;
}

// One warp per node: reduce s-row (256 f32) and v-row (384 f32).
__global__ __launch_bounds__(256) void reduce_kernel(
    const float* __restrict__ s, const float* __restrict__ v,
    const int* __restrict__ batch, int n)
{
    int warp = (blockIdx.x * blockDim.x + threadIdx.x) >> 5;
    int lane = threadIdx.x & 31;
    if (warp >= n) return;

    const float4* srow = (const float4*)(s + (size_t)warp * 256);
    const float4* vrow = (const float4*)(v + (size_t)warp * 384);

    float4 x0 = srow[lane];
    float4 x1 = srow[lane + 32];
    float4 y0 = vrow[lane];
    float4 y1 = vrow[lane + 32];
    float4 y2 = vrow[lane + 64];

    float sa = sum4(x0) + sum4(x1);
    float sb = dot4(x0, x0) + dot4(x1, x1);
    float sw = dot4(y0, y0) + dot4(y1, y1) + dot4(y2, y2);

    #pragma unroll
    for (int o = 16; o > 0; o >>= 1) {
        sa += __shfl_xor_sync(0xFFFFFFFFu, sa, o);
        sb += __shfl_xor_sync(0xFFFFFFFFu, sb, o);
        sw += __shfl_xor_sync(0xFFFFFFFFu, sw, o);
    }

    if (lane == 0) {
        int seg = batch[warp];
        atomicAdd(&g_sumA[seg], sa * (1.f / 256.f));
        atomicAdd(&g_sumB[seg], sb * (1.f / 256.f));
        atomicAdd(&g_sumW[seg], sw * (1.f / 128.f));
        atomicAdd(&g_cnt[seg],  1.f);
    }
}

__global__ void stats_kernel() {
    int i = blockIdx.x * blockDim.x + threadIdx.x;
    if (i < NSEG) {
        float c  = fmaxf(g_cnt[i], 1.f);
        float sm = g_sumA[i] / c;
        float var = fmaxf(g_sumB[i] / c - sm * sm, EPS);
        float vm  = fmaxf(g_sumW[i] / c, EPS);
        g_smean[i]  = sm;
        g_invvar[i] = 1.f / var;
        g_invvm[i]  = 1.f / vm;
    }
}

// One warp per node: normalize s and v, write both outputs.
__global__ __launch_bounds__(256) void apply_kernel(
    const float* __restrict__ s, const float* __restrict__ v,
    const float* __restrict__ weight, const float* __restrict__ bias,
    const int* __restrict__ batch,
    float* __restrict__ sout, float* __restrict__ vout, int n)
{
    int warp = (blockIdx.x * blockDim.x + threadIdx.x) >> 5;
    int lane = threadIdx.x & 31;
    if (warp >= n) return;

    const float4* srow = (const float4*)(s + (size_t)warp * 256);
    const float4* vrow = (const float4*)(v + (size_t)warp * 384);
    float4*       so   = (float4*)(sout + (size_t)warp * 256);
    float4*       vo   = (float4*)(vout + (size_t)warp * 384);

    // Issue bulk data loads first (independent of the seg-stat chain).
    float4 x0 = srow[lane];
    float4 x1 = srow[lane + 32];
    float4 y0 = vrow[lane];
    float4 y1 = vrow[lane + 32];
    float4 y2 = vrow[lane + 64];
    float4 w0 = ((const float4*)weight)[lane];
    float4 w1 = ((const float4*)weight)[lane + 32];
    float4 b0 = ((const float4*)bias)[lane];
    float4 b1 = ((const float4*)bias)[lane + 32];

    int seg   = batch[warp];          // warp-uniform, L2-resident
    float sm  = g_smean[seg];
    float iva = g_invvar[seg];
    float ivm = g_invvm[seg];

    float4 o0, o1;
    o0.x = (x0.x - sm) * iva * w0.x + b0.x;
    o0.y = (x0.y - sm) * iva * w0.y + b0.y;
    o0.z = (x0.z - sm) * iva * w0.z + b0.z;
    o0.w = (x0.w - sm) * iva * w0.w + b0.w;
    o1.x = (x1.x - sm) * iva * w1.x + b1.x;
    o1.y = (x1.y - sm) * iva * w1.y + b1.y;
    o1.z = (x1.z - sm) * iva * w1.z + b1.z;
    o1.w = (x1.w - sm) * iva * w1.w + b1.w;
    so[lane]      = o0;
    so[lane + 32] = o1;

    float4 z0, z1, z2;
    z0.x = y0.x * ivm; z0.y = y0.y * ivm; z0.z = y0.z * ivm; z0.w = y0.w * ivm;
    z1.x = y1.x * ivm; z1.y = y1.y * ivm; z1.z = y1.z * ivm; z1.w = y1.w * ivm;
    z2.x = y2.x * ivm; z2.y = y2.y * ivm; z2.z = y2.z * ivm; z2.w = y2.w * ivm;
    vo[lane]      = z0;
    vo[lane + 32] = z1;
    vo[lane + 64] = z2;
}

extern "C" void kernel_launch(void* const* d_in, const int* in_sizes, int n_in,
                              void* d_out, int out_size)
{
    const float* s      = (const float*)d_in[0];
    const float* v      = (const float*)d_in[1];
    const float* weight = (const float*)d_in[2];
    const float* bias   = (const float*)d_in[3];
    const int*   batch  = (const int*)d_in[4];

    int n = in_sizes[0] / 256;          // number of nodes
    float* sout = (float*)d_out;
    float* vout = (float*)d_out + (size_t)n * 256;

    zero_kernel<<<(NSEG + 255) / 256, 256>>>();

    int blocks = (n + 7) / 8;           // 8 warps/block, warp per node
    reduce_kernel<<<blocks, 256>>>(s, v, batch, n);

    stats_kernel<<<(NSEG + 255) / 256, 256>>>();

    apply_kernel<<<blocks, 256>>>(s, v, weight, bias, batch, sout, vout, n);
}

// round 2
// speedup vs baseline: 1.1441x; 1.1441x over previous
#include <cuda_runtime.h>
#include <cuda_bf16.h>

#define NSEG 2048
#define EPS 1e-6f

// Segment start offsets derived from the sorted batch array. g_start[NSEG] = n.
__device__ int g_start[NSEG + 1];

__global__ void find_starts(const int* __restrict__ batch, int n) {
    int i = blockIdx.x * blockDim.x + threadIdx.x;
    if (i >= n) return;
    int b    = batch[i];
    int prev = (i == 0) ? -1 : batch[i - 1];
    for (int seg = prev + 1; seg <= b; ++seg) g_start[seg] = i;
    if (i == n - 1) {
        for (int seg = b + 1; seg <= NSEG; ++seg) g_start[seg] = n;
    }
}

__device__ __forceinline__ float dot4(float4 a, float4 b) {
    return a.x * b.x + a.y * b.y + a.z * b.z + a.w * b.w;
}
__device__ __forceinline__ float sum4(float4 a) {
    return a.x + a.y + a.z + a.w;
}

// One CTA per segment. Pass 1: reduce stats over the segment's contiguous
// node range. Pass 2: normalize — re-reads hit L2 (just-read, ~400KB/segment,
// <=148 concurrent CTAs -> ~59MB in flight < 126MB L2).
__global__ __launch_bounds__(512, 1) void fused_kernel(
    const float* __restrict__ s, const float* __restrict__ v,
    const float* __restrict__ weight, const float* __restrict__ bias,
    float* __restrict__ sout, float* __restrict__ vout)
{
    __shared__ float sh_acc[3];
    __shared__ float sh_stat[3];

    int seg = blockIdx.x;
    int n0 = g_start[seg];
    int n1 = g_start[seg + 1];
    int cnt = n1 - n0;
    if (cnt == 0) return;           // empty segment: no nodes, nothing to write

    int warp = threadIdx.x >> 5;    // 16 warps
    int lane = threadIdx.x & 31;

    if (threadIdx.x == 0) { sh_acc[0] = 0.f; sh_acc[1] = 0.f; sh_acc[2] = 0.f; }
    __syncthreads();

    // ---- pass 1: stats ----
    float sa = 0.f, sb = 0.f, sw = 0.f;
    for (int node = n0 + warp; node < n1; node += 16) {
        const float4* srow = (const float4*)(s + (size_t)node * 256);
        const float4* vrow = (const float4*)(v + (size_t)node * 384);
        float4 x0 = srow[lane];
        float4 x1 = srow[lane + 32];
        float4 y0 = vrow[lane];
        float4 y1 = vrow[lane + 32];
        float4 y2 = vrow[lane + 64];
        sa += sum4(x0) + sum4(x1);
        sb += dot4(x0, x0) + dot4(x1, x1);
        sw += dot4(y0, y0) + dot4(y1, y1) + dot4(y2, y2);
    }
    #pragma unroll
    for (int o = 16; o > 0; o >>= 1) {
        sa += __shfl_xor_sync(0xFFFFFFFFu, sa, o);
        sb += __shfl_xor_sync(0xFFFFFFFFu, sb, o);
        sw += __shfl_xor_sync(0xFFFFFFFFu, sw, o);
    }
    if (lane == 0) {
        atomicAdd(&sh_acc[0], sa);
        atomicAdd(&sh_acc[1], sb);
        atomicAdd(&sh_acc[2], sw);
    }
    __syncthreads();

    if (threadIdx.x == 0) {
        float c   = (float)cnt;
        float sm  = sh_acc[0] * (1.f / 256.f) / c;
        float ex2 = sh_acc[1] * (1.f / 256.f) / c;
        float var = fmaxf(ex2 - sm * sm, EPS);
        float vm  = fmaxf(sh_acc[2] * (1.f / 128.f) / c, EPS);
        sh_stat[0] = sm;
        sh_stat[1] = 1.f / var;
        sh_stat[2] = 1.f / vm;
    }
    __syncthreads();

    float sm  = sh_stat[0];
    float iva = sh_stat[1];
    float ivm = sh_stat[2];

    float4 w0 = ((const float4*)weight)[lane];
    float4 w1 = ((const float4*)weight)[lane + 32];
    float4 b0 = ((const float4*)bias)[lane];
    float4 b1 = ((const float4*)bias)[lane + 32];

    // ---- pass 2: normalize (reads served from L2) ----
    for (int node = n0 + warp; node < n1; node += 16) {
        const float4* srow = (const float4*)(s + (size_t)node * 256);
        const float4* vrow = (const float4*)(v + (size_t)node * 384);
        float4*       so   = (float4*)(sout + (size_t)node * 256);
        float4*       vo   = (float4*)(vout + (size_t)node * 384);

        float4 x0 = srow[lane];
        float4 x1 = srow[lane + 32];
        float4 y0 = vrow[lane];
        float4 y1 = vrow[lane + 32];
        float4 y2 = vrow[lane + 64];

        float4 o0, o1;
        o0.x = (x0.x - sm) * iva * w0.x + b0.x;
        o0.y = (x0.y - sm) * iva * w0.y + b0.y;
        o0.z = (x0.z - sm) * iva * w0.z + b0.z;
        o0.w = (x0.w - sm) * iva * w0.w + b0.w;
        o1.x = (x1.x - sm) * iva * w1.x + b1.x;
        o1.y = (x1.y - sm) * iva * w1.y + b1.y;
        o1.z = (x1.z - sm) * iva * w1.z + b1.z;
        o1.w = (x1.w - sm) * iva * w1.w + b1.w;
        so[lane]      = o0;
        so[lane + 32] = o1;

        float4 z0, z1, z2;
        z0.x = y0.x * ivm; z0.y = y0.y * ivm; z0.z = y0.z * ivm; z0.w = y0.w * ivm;
        z1.x = y1.x * ivm; z1.y = y1.y * ivm; z1.z = y1.z * ivm; z1.w = y1.w * ivm;
        z2.x = y2.x * ivm; z2.y = y2.y * ivm; z2.z = y2.z * ivm; z2.w = y2.w * ivm;
        vo[lane]      = z0;
        vo[lane + 32] = z1;
        vo[lane + 64] = z2;
    }
}

extern "C" void kernel_launch(void* const* d_in, const int* in_sizes, int n_in,
                              void* d_out, int out_size)
{
    const float* s      = (const float*)d_in[0];
    const float* v      = (const float*)d_in[1];
    const float* weight = (const float*)d_in[2];
    const float* bias   = (const float*)d_in[3];
    const int*   batch  = (const int*)d_in[4];

    int n = in_sizes[0] / 256;
    float* sout = (float*)d_out;
    float* vout = (float*)d_out + (size_t)n * 256;

    find_starts<<<(n + 255) / 256, 256>>>(batch, n);
    fused_kernel<<<NSEG, 512>>>(s, v, weight, bias, sout, vout);
}

// round 3
// speedup vs baseline: 1.3707x; 1.1981x over previous
#include <cuda_runtime.h>
#include <cuda_bf16.h>

#define NSEG 2048
#define EPS 1e-6f

// Segment start offsets derived from the sorted batch array. g_start[NSEG] = n.
__device__ int g_start[NSEG + 1];

__global__ void find_starts(const int* __restrict__ batch, int n) {
    int i = blockIdx.x * blockDim.x + threadIdx.x;
    if (i >= n) return;
    int b    = batch[i];
    int prev = (i == 0) ? -1 : batch[i - 1];
    for (int seg = prev + 1; seg <= b; ++seg) g_start[seg] = i;
    if (i == n - 1) {
        for (int seg = b + 1; seg <= NSEG; ++seg) g_start[seg] = n;
    }
}

__device__ __forceinline__ float dot4(float4 a, float4 b) {
    return a.x * b.x + a.y * b.y + a.z * b.z + a.w * b.w;
}
__device__ __forceinline__ float sum4(float4 a) {
    return a.x + a.y + a.z + a.w;
}

// One CTA per segment. Pass 1: reduce stats over the segment's contiguous
// node range (default .ca loads -> resident in L2). Pass 2: normalize,
// traversing in REVERSE so the most-recently-read lines are re-read first;
// re-reads use .cs (evict-first) and outputs use streaming stores so they
// don't evict other CTAs' pass-1 data.
__global__ __launch_bounds__(512, 1) void fused_kernel(
    const float* __restrict__ s, const float* __restrict__ v,
    const float* __restrict__ weight, const float* __restrict__ bias,
    float* __restrict__ sout, float* __restrict__ vout)
{
    __shared__ float sh_acc[3];
    __shared__ float sh_stat[3];

    int seg = blockIdx.x;
    int n0 = g_start[seg];
    int n1 = g_start[seg + 1];
    int cnt = n1 - n0;
    if (cnt == 0) return;           // empty segment: nothing to write

    int warp = threadIdx.x >> 5;    // 16 warps
    int lane = threadIdx.x & 31;

    if (threadIdx.x == 0) { sh_acc[0] = 0.f; sh_acc[1] = 0.f; sh_acc[2] = 0.f; }
    __syncthreads();

    // ---- pass 1: stats (forward traversal) ----
    float sa = 0.f, sb = 0.f, sw = 0.f;
    for (int node = n0 + warp; node < n1; node += 16) {
        const float4* srow = (const float4*)(s + (size_t)node * 256);
        const float4* vrow = (const float4*)(v + (size_t)node * 384);
        float4 x0 = srow[lane];
        float4 x1 = srow[lane + 32];
        float4 y0 = vrow[lane];
        float4 y1 = vrow[lane + 32];
        float4 y2 = vrow[lane + 64];
        sa += sum4(x0) + sum4(x1);
        sb += dot4(x0, x0) + dot4(x1, x1);
        sw += dot4(y0, y0) + dot4(y1, y1) + dot4(y2, y2);
    }
    #pragma unroll
    for (int o = 16; o > 0; o >>= 1) {
        sa += __shfl_xor_sync(0xFFFFFFFFu, sa, o);
        sb += __shfl_xor_sync(0xFFFFFFFFu, sb, o);
        sw += __shfl_xor_sync(0xFFFFFFFFu, sw, o);
    }
    if (lane == 0) {
        atomicAdd(&sh_acc[0], sa);
        atomicAdd(&sh_acc[1], sb);
        atomicAdd(&sh_acc[2], sw);
    }
    __syncthreads();

    if (threadIdx.x == 0) {
        float c   = (float)cnt;
        float sm  = sh_acc[0] * (1.f / 256.f) / c;
        float ex2 = sh_acc[1] * (1.f / 256.f) / c;
        float var = fmaxf(ex2 - sm * sm, EPS);
        float vm  = fmaxf(sh_acc[2] * (1.f / 128.f) / c, EPS);
        sh_stat[0] = sm;
        sh_stat[1] = 1.f / var;
        sh_stat[2] = 1.f / vm;
    }
    __syncthreads();

    float sm  = sh_stat[0];
    float iva = sh_stat[1];
    float ivm = sh_stat[2];

    float4 w0 = ((const float4*)weight)[lane];
    float4 w1 = ((const float4*)weight)[lane + 32];
    float4 b0 = ((const float4*)bias)[lane];
    float4 b1 = ((const float4*)bias)[lane + 32];

    // ---- pass 2: normalize (REVERSE traversal, MRU-first; streaming) ----
    for (int node = n1 - 1 - warp; node >= n0; node -= 16) {
        const float4* srow = (const float4*)(s + (size_t)node * 256);
        const float4* vrow = (const float4*)(v + (size_t)node * 384);
        float4*       so   = (float4*)(sout + (size_t)node * 256);
        float4*       vo   = (float4*)(vout + (size_t)node * 384);

        float4 x0 = __ldcs(srow + lane);
        float4 x1 = __ldcs(srow + lane + 32);
        float4 y0 = __ldcs(vrow + lane);
        float4 y1 = __ldcs(vrow + lane + 32);
        float4 y2 = __ldcs(vrow + lane + 64);

        float4 o0, o1;
        o0.x = (x0.x - sm) * iva * w0.x + b0.x;
        o0.y = (x0.y - sm) * iva * w0.y + b0.y;
        o0.z = (x0.z - sm) * iva * w0.z + b0.z;
        o0.w = (x0.w - sm) * iva * w0.w + b0.w;
        o1.x = (x1.x - sm) * iva * w1.x + b1.x;
        o1.y = (x1.y - sm) * iva * w1.y + b1.y;
        o1.z = (x1.z - sm) * iva * w1.z + b1.z;
        o1.w = (x1.w - sm) * iva * w1.w + b1.w;
        __stcs(so + lane,      o0);
        __stcs(so + lane + 32, o1);

        float4 z0, z1, z2;
        z0.x = y0.x * ivm; z0.y = y0.y * ivm; z0.z = y0.z * ivm; z0.w = y0.w * ivm;
        z1.x = y1.x * ivm; z1.y = y1.y * ivm; z1.z = y1.z * ivm; z1.w = y1.w * ivm;
        z2.x = y2.x * ivm; z2.y = y2.y * ivm; z2.z = y2.z * ivm; z2.w = y2.w * ivm;
        __stcs(vo + lane,      z0);
        __stcs(vo + lane + 32, z1);
        __stcs(vo + lane + 64, z2);
    }
}

extern "C" void kernel_launch(void* const* d_in, const int* in_sizes, int n_in,
                              void* d_out, int out_size)
{
    const float* s      = (const float*)d_in[0];
    const float* v      = (const float*)d_in[1];
    const float* weight = (const float*)d_in[2];
    const float* bias   = (const float*)d_in[3];
    const int*   batch  = (const int*)d_in[4];

    int n = in_sizes[0] / 256;
    float* sout = (float*)d_out;
    float* vout = (float*)d_out + (size_t)n * 256;

    find_starts<<<(n + 255) / 256, 256>>>(batch, n);
    fused_kernel<<<NSEG, 512>>>(s, v, weight, bias, sout, vout);
}